// round 17
// baseline (speedup 1.0000x reference)
#include <cuda_runtime.h>
#include <math.h>
#include <cstdint>

// ---------------- problem constants ----------------
#define BATCH 16
#define SEQ   512
#define SIN   384
#define SRES  129
#define WID   1024
#define HEADS 16
#define DHEAD 64
#define DFF   4096
#define NTOP  50
#define NGRP  7
#define MROWS (BATCH*SEQ)   // 8192

// ---------------- scratch ----------------
__device__ float g_qkv[(size_t)MROWS * 3072];
__device__ float g_ctx[(size_t)MROWS * WID];
__device__ float g_tmp[(size_t)MROWS * DFF];
__device__ float g_y  [(size_t)MROWS * WID];
__device__ float g_hid[(size_t)MROWS * WID];      // rounded+permuted X early, hidden late
__device__ float g_wr [12582912];                  // rounded+permuted weights
__device__ float g_mp [NGRP * BATCH * WID];
__device__ float g_ue [NGRP * BATCH * WID];

// round-to-nearest tf32
__device__ __forceinline__ uint32_t f2tf(float x) {
    uint32_t r;
    asm("cvt.rna.tf32.f32 %0, %1;" : "=r"(r) : "f"(x));
    return r;
}
__device__ __forceinline__ float rtf(float x) { return __uint_as_float(f2tf(x)); }

__device__ __forceinline__ void mma_tf32(float* c, const uint32_t* a, const uint32_t* b) {
    asm volatile(
        "mma.sync.aligned.m16n8k8.row.col.f32.tf32.tf32.f32 "
        "{%0,%1,%2,%3}, {%4,%5,%6,%7}, {%8,%9}, {%0,%1,%2,%3};"
        : "+f"(c[0]), "+f"(c[1]), "+f"(c[2]), "+f"(c[3])
        : "r"(a[0]), "r"(a[1]), "r"(a[2]), "r"(a[3]), "r"(b[0]), "r"(b[1]));
}

__device__ __forceinline__ void cpa16(void* dst, const float* src) {
    uint32_t d = (uint32_t)__cvta_generic_to_shared(dst);
    asm volatile("cp.async.cg.shared.global [%0], [%1], 16;" :: "r"(d), "l"(src));
}

// ---------------- fused multi-tensor tf32 round + K-group permute ----------------
// permutation per 8-group: stored[2j] = orig[j], stored[2j+1] = orig[j+4]
__global__ __launch_bounds__(256) void round_perm_multi(
    const float* s0, float* d0, int n0,
    const float* s1, float* d1, int n1,
    const float* s2, float* d2, int n2,
    const float* s3, float* d3, int n3,
    const float* s4, float* d4, int n4)   // counts in float8 units
{
    int total = n0 + n1 + n2 + n3 + n4;
    for (int idx = blockIdx.x * 256 + threadIdx.x; idx < total; idx += gridDim.x * 256) {
        int i = idx;
        const float* s; float* d;
        if (i < n0) { s = s0; d = d0; }
        else { i -= n0;
            if (i < n1) { s = s1; d = d1; }
            else { i -= n1;
                if (i < n2) { s = s2; d = d2; }
                else { i -= n2;
                    if (i < n3) { s = s3; d = d3; }
                    else { i -= n3; s = s4; d = d4; } } } }
        float4 lo = *(const float4*)(s + (size_t)i * 8);
        float4 hi = *(const float4*)(s + (size_t)i * 8 + 4);
        float4 w0, w1;
        w0.x = rtf(lo.x); w0.y = rtf(hi.x); w0.z = rtf(lo.y); w0.w = rtf(hi.y);
        w1.x = rtf(lo.z); w1.y = rtf(hi.z); w1.z = rtf(lo.w); w1.w = rtf(hi.w);
        *(float4*)(d + (size_t)i * 8)     = w0;
        *(float4*)(d + (size_t)i * 8 + 4) = w1;
    }
}

// ================= TF32 tensor-core GEMM (permuted-K operands) =================
// (unchanged — proven config: 128 thr, warp tile 64x64, 1 sync/K-iter)
#define BM 128
#define BN 128
#define BK 32
#define NSTAGE 3
#define STAGE_F (BM * BK)    // 4096 floats per operand per stage

__global__ __launch_bounds__(128, 2) void mma_gemm(
    const float* __restrict__ A, const float* __restrict__ Bw,
    const float* __restrict__ bias, float* __restrict__ C,
    int M, int N, int K, int mode)
{
    extern __shared__ float smbuf[];
    float* As = smbuf;
    float* Bs = smbuf + NSTAGE * STAGE_F;

    const int tid  = threadIdx.x;
    const int m0   = blockIdx.y * BM;
    const int n0   = blockIdx.x * BN;
    const int warp = tid >> 5, lane = tid & 31;
    const int g    = lane >> 2, tig = lane & 3;
    const int mw   = (warp >> 1) * 64;   // 0 or 64
    const int nw   = (warp & 1) * 64;    // 0 or 64

    float acc[4][8][4];
    #pragma unroll
    for (int mi = 0; mi < 4; mi++)
        #pragma unroll
        for (int ni = 0; ni < 8; ni++)
            #pragma unroll
            for (int r = 0; r < 4; r++) acc[mi][ni][r] = 0.0f;

    const int kiters = K / BK;

    const int swz = (g & 3) << 1;
    const int t2  = tig >> 1;
    const int tl  = (tig & 1) << 1;
    int koff[4];
    #pragma unroll
    for (int j = 0; j < 4; j++) koff[j] = (((j << 1) ^ swz) << 2);
    int rA[4], rB[8];
    #pragma unroll
    for (int mi = 0; mi < 4; mi++) rA[mi] = (mw + mi * 16 + g) * 32 + 4 * t2 + tl;
    #pragma unroll
    for (int ni = 0; ni < 8; ni++) rB[ni] = (nw + ni * 8 + g) * 32 + 4 * t2 + tl;

    #pragma unroll
    for (int s = 0; s < NSTAGE - 1; s++) {
        const int k0 = s * BK;
        #pragma unroll
        for (int i = 0; i < 8; i++) {
            int c = tid + (i << 7);
            int row = c >> 3, ch = c & 7;
            int dst = row * 32 + ((ch ^ ((row & 3) << 1)) << 2);
            cpa16(As + s * STAGE_F + dst, A  + (size_t)(m0 + row) * K + k0 + ch * 4);
            cpa16(Bs + s * STAGE_F + dst, Bw + (size_t)(n0 + row) * K + k0 + ch * 4);
        }
        asm volatile("cp.async.commit_group;");
    }

    for (int kt = 0; kt < kiters; kt++) {
        asm volatile("cp.async.wait_group %0;" :: "n"(NSTAGE - 2));
        __syncthreads();

        const int ps = kt + NSTAGE - 1;
        if (ps < kiters) {
            const int s = ps % NSTAGE;
            const int k0 = ps * BK;
            #pragma unroll
            for (int i = 0; i < 8; i++) {
                int c = tid + (i << 7);
                int row = c >> 3, ch = c & 7;
                int dst = row * 32 + ((ch ^ ((row & 3) << 1)) << 2);
                cpa16(As + s * STAGE_F + dst, A  + (size_t)(m0 + row) * K + k0 + ch * 4);
                cpa16(Bs + s * STAGE_F + dst, Bw + (size_t)(n0 + row) * K + k0 + ch * 4);
            }
        }
        asm volatile("cp.async.commit_group;");   // always (empty in tail)

        const float* as = As + (kt % NSTAGE) * STAGE_F;
        const float* bs = Bs + (kt % NSTAGE) * STAGE_F;

        #pragma unroll
        for (int j = 0; j < 4; j++) {
            uint32_t af[4][4], bf[8][2];
            #pragma unroll
            for (int mi = 0; mi < 4; mi++) {
                float2 x1 = *(const float2*)(as + rA[mi] + koff[j]);
                float2 x2 = *(const float2*)(as + rA[mi] + 256 + koff[j]);
                af[mi][0] = __float_as_uint(x1.x);
                af[mi][2] = __float_as_uint(x1.y);
                af[mi][1] = __float_as_uint(x2.x);
                af[mi][3] = __float_as_uint(x2.y);
            }
            #pragma unroll
            for (int ni = 0; ni < 8; ni++) {
                float2 y = *(const float2*)(bs + rB[ni] + koff[j]);
                bf[ni][0] = __float_as_uint(y.x);
                bf[ni][1] = __float_as_uint(y.y);
            }
            #pragma unroll
            for (int mi = 0; mi < 4; mi++)
                #pragma unroll
                for (int ni = 0; ni < 8; ni++)
                    mma_tf32(acc[mi][ni], af[mi], bf[ni]);
        }
    }

    const bool dogelu  = (mode & 1) != 0;
    const bool doround = (mode & 2) != 0;
    const bool doperm  = (mode & 4) != 0;
    const int  p0 = (tig < 2) ? 4 * tig     : 4 * tig - 7;
    const int  p1 = (tig < 2) ? 4 * tig + 2 : 4 * tig - 5;
    #pragma unroll
    for (int ni = 0; ni < 8; ni++) {
        const int gb = n0 + nw + ni * 8;
        const int cc = gb + 2 * tig;
        const float bv0 = bias[cc], bv1 = bias[cc + 1];
        #pragma unroll
        for (int mi = 0; mi < 4; mi++) {
            const int r0 = m0 + mw + mi * 16 + g;
            float v00 = acc[mi][ni][0] + bv0;
            float v01 = acc[mi][ni][1] + bv1;
            float v10 = acc[mi][ni][2] + bv0;
            float v11 = acc[mi][ni][3] + bv1;
            if (dogelu) {
                v00 = 0.5f * v00 * (1.0f + erff(v00 * 0.70710678118654752f));
                v01 = 0.5f * v01 * (1.0f + erff(v01 * 0.70710678118654752f));
                v10 = 0.5f * v10 * (1.0f + erff(v10 * 0.70710678118654752f));
                v11 = 0.5f * v11 * (1.0f + erff(v11 * 0.70710678118654752f));
            }
            if (doround) {
                v00 = rtf(v00); v01 = rtf(v01); v10 = rtf(v10); v11 = rtf(v11);
            }
            if (doperm) {
                C[(size_t)r0 * N + gb + p0]       = v00;
                C[(size_t)r0 * N + gb + p1]       = v01;
                C[(size_t)(r0 + 8) * N + gb + p0] = v10;
                C[(size_t)(r0 + 8) * N + gb + p1] = v11;
            } else {
                *(float2*)(C + (size_t)r0 * N + cc)       = make_float2(v00, v01);
                *(float2*)(C + (size_t)(r0 + 8) * N + cc) = make_float2(v10, v11);
            }
        }
    }
}

// ================= tensor-core flash attention (tf32, d-axis permuted) =============
// (unchanged — cp.async double-buffered K/V, shuffle-relayed P)
#define QP 72

__global__ __launch_bounds__(256, 2) void attn_mma_kernel(
    const float* __restrict__ qkv, float* __restrict__ ctx)
{
    __shared__ float Qs[128][QP];
    __shared__ float Ks[2][64][QP];
    __shared__ float Vs[2][64][QP];

    const int bh = blockIdx.y;
    const int b = bh >> 4, h = bh & 15;
    const int q0 = blockIdx.x * 128;
    const int tid = threadIdx.x;
    const int warp = tid >> 5, lane = tid & 31;
    const int g = lane >> 2, t = lane & 3;
    const int mw = warp * 16;

    #pragma unroll
    for (int i = 0; i < 8; i++) {
        int idx = tid + i * 256;
        int row = idx >> 4, c4 = (idx & 15) * 4;
        float4 v = *(const float4*)(qkv + (size_t)(b*SEQ + q0 + row) * 3072 + h*DHEAD + c4);
        v.x *= 0.125f; v.y *= 0.125f; v.z *= 0.125f; v.w *= 0.125f;
        *(float4*)&Qs[row][c4] = v;
    }

    auto stage_kv = [&](int kb, int buf) {
        #pragma unroll
        for (int i = 0; i < 4; i++) {
            int c = tid + (i << 8);
            int row = c >> 4, ch = c & 15;
            const float* base = qkv + (size_t)(b*SEQ + kb + row) * 3072 + h*DHEAD + ch * 4;
            cpa16(&Ks[buf][row][ch * 4], base + 1024);
            cpa16(&Vs[buf][row][ch * 4], base + 2048);
        }
    };

    float o[8][4];
    #pragma unroll
    for (int nt = 0; nt < 8; nt++)
        #pragma unroll
        for (int r = 0; r < 4; r++) o[nt][r] = 0.0f;
    float m0 = -1e30f, m1 = -1e30f, l0 = 0.0f, l1 = 0.0f;

    stage_kv(0, 0);
    asm volatile("cp.async.commit_group;");

    for (int it = 0; it < 8; it++) {
        const int cur = it & 1;
        if (it < 7) stage_kv((it + 1) * 64, (it + 1) & 1);
        asm volatile("cp.async.commit_group;");
        asm volatile("cp.async.wait_group 1;");
        __syncthreads();

        float sacc[8][4];
        #pragma unroll
        for (int nt = 0; nt < 8; nt++)
            #pragma unroll
            for (int r = 0; r < 4; r++) sacc[nt][r] = 0.0f;

        #pragma unroll
        for (int kt = 0; kt < 8; kt++) {
            uint32_t af[4];
            float2 q1 = *(const float2*)&Qs[mw + g][kt*8 + 2*t];
            float2 q2 = *(const float2*)&Qs[mw + g + 8][kt*8 + 2*t];
            af[0] = __float_as_uint(q1.x); af[2] = __float_as_uint(q1.y);
            af[1] = __float_as_uint(q2.x); af[3] = __float_as_uint(q2.y);
            #pragma unroll
            for (int nt = 0; nt < 8; nt++) {
                uint32_t bf[2];
                float2 kv = *(const float2*)&Ks[cur][nt*8 + g][kt*8 + 2*t];
                bf[0] = __float_as_uint(kv.x); bf[1] = __float_as_uint(kv.y);
                mma_tf32(sacc[nt], af, bf);
            }
        }

        float rmax0 = -1e30f, rmax1 = -1e30f;
        #pragma unroll
        for (int nt = 0; nt < 8; nt++) {
            rmax0 = fmaxf(rmax0, fmaxf(sacc[nt][0], sacc[nt][1]));
            rmax1 = fmaxf(rmax1, fmaxf(sacc[nt][2], sacc[nt][3]));
        }
        #pragma unroll
        for (int d = 1; d < 4; d <<= 1) {
            rmax0 = fmaxf(rmax0, __shfl_xor_sync(0xffffffffu, rmax0, d));
            rmax1 = fmaxf(rmax1, __shfl_xor_sync(0xffffffffu, rmax1, d));
        }
        float m0n = fmaxf(m0, rmax0), m1n = fmaxf(m1, rmax1);
        float c0 = __expf(m0 - m0n), c1 = __expf(m1 - m1n);
        m0 = m0n; m1 = m1n;

        float sum0 = 0.0f, sum1 = 0.0f;
        #pragma unroll
        for (int nt = 0; nt < 8; nt++) {
            sacc[nt][0] = __expf(sacc[nt][0] - m0);
            sacc[nt][1] = __expf(sacc[nt][1] - m0);
            sacc[nt][2] = __expf(sacc[nt][2] - m1);
            sacc[nt][3] = __expf(sacc[nt][3] - m1);
            sum0 += sacc[nt][0] + sacc[nt][1];
            sum1 += sacc[nt][2] + sacc[nt][3];
        }
        #pragma unroll
        for (int d = 1; d < 4; d <<= 1) {
            sum0 += __shfl_xor_sync(0xffffffffu, sum0, d);
            sum1 += __shfl_xor_sync(0xffffffffu, sum1, d);
        }
        l0 = l0 * c0 + sum0;
        l1 = l1 * c1 + sum1;
        #pragma unroll
        for (int nt = 0; nt < 8; nt++) {
            o[nt][0] *= c0; o[nt][1] *= c0;
            o[nt][2] *= c1; o[nt][3] *= c1;
        }

        #pragma unroll
        for (int nt = 0; nt < 8; nt++) {
            sacc[nt][0] = rtf(sacc[nt][0]);
            sacc[nt][1] = rtf(sacc[nt][1]);
            sacc[nt][2] = rtf(sacc[nt][2]);
            sacc[nt][3] = rtf(sacc[nt][3]);
        }

        const int L1 = (lane & 28) | (t >> 1);
        #pragma unroll
        for (int kt = 0; kt < 8; kt++) {
            float s0a = __shfl_sync(0xffffffffu, sacc[kt][0], L1);
            float s1a = __shfl_sync(0xffffffffu, sacc[kt][1], L1);
            float s2a = __shfl_sync(0xffffffffu, sacc[kt][2], L1);
            float s3a = __shfl_sync(0xffffffffu, sacc[kt][3], L1);
            float s0b = __shfl_sync(0xffffffffu, sacc[kt][0], L1 + 2);
            float s1b = __shfl_sync(0xffffffffu, sacc[kt][1], L1 + 2);
            float s2b = __shfl_sync(0xffffffffu, sacc[kt][2], L1 + 2);
            float s3b = __shfl_sync(0xffffffffu, sacc[kt][3], L1 + 2);
            uint32_t af[4];
            af[0] = __float_as_uint((t & 1) ? s1a : s0a);
            af[1] = __float_as_uint((t & 1) ? s3a : s2a);
            af[2] = __float_as_uint((t & 1) ? s1b : s0b);
            af[3] = __float_as_uint((t & 1) ? s3b : s2b);
            #pragma unroll
            for (int nt = 0; nt < 8; nt++) {
                uint32_t bf[2];
                bf[0] = __float_as_uint(Vs[cur][kt*8 + t][nt*8 + g]);
                bf[1] = __float_as_uint(Vs[cur][kt*8 + t + 4][nt*8 + g]);
                mma_tf32(o[nt], af, bf);
            }
        }
        __syncthreads();
    }

    float inv0 = 1.0f / l0, inv1 = 1.0f / l1;
    const int r0 = b*SEQ + q0 + mw + g;
    const int cbase = h*DHEAD + 2*t;
    #pragma unroll
    for (int nt = 0; nt < 8; nt++) {
        *(float2*)(ctx + (size_t)r0 * WID + cbase + nt*8) =
            make_float2(rtf(o[nt][0]*inv0), rtf(o[nt][1]*inv0));
        *(float2*)(ctx + (size_t)(r0 + 8) * WID + cbase + nt*8) =
            make_float2(rtf(o[nt][2]*inv1), rtf(o[nt][3]*inv1));
    }
}

// ---------------- residual add + LayerNorm (+ optional rounded PERMUTED copy) -------
__global__ __launch_bounds__(256) void add_ln_kernel(
    const float* __restrict__ resid, const float* __restrict__ x,
    const float* __restrict__ gg, const float* __restrict__ bb,
    float* __restrict__ out, float* __restrict__ outr)
{
    __shared__ float2 sm[8];
    const size_t row = blockIdx.x;
    const int tid = threadIdx.x;

    float4 r = *(const float4*)(resid + row*WID + tid*4);
    float4 v = *(const float4*)(x     + row*WID + tid*4);
    float4 tv;
    tv.x = r.x + v.x; tv.y = r.y + v.y; tv.z = r.z + v.z; tv.w = r.w + v.w;

    float s = tv.x + tv.y + tv.z + tv.w;
    float qq = tv.x*tv.x + tv.y*tv.y + tv.z*tv.z + tv.w*tv.w;

    int lane = tid & 31, warp = tid >> 5;
    #pragma unroll
    for (int o = 16; o > 0; o >>= 1) {
        s  += __shfl_down_sync(0xffffffffu, s,  o);
        qq += __shfl_down_sync(0xffffffffu, qq, o);
    }
    if (lane == 0) sm[warp] = make_float2(s, qq);
    __syncthreads();
    if (warp == 0) {
        float2 w2 = (lane < 8) ? sm[lane] : make_float2(0.f, 0.f);
        #pragma unroll
        for (int o = 4; o > 0; o >>= 1) {
            w2.x += __shfl_down_sync(0xffffffffu, w2.x, o);
            w2.y += __shfl_down_sync(0xffffffffu, w2.y, o);
        }
        if (lane == 0) sm[0] = w2;
    }
    __syncthreads();
    float mean = sm[0].x * (1.0f/WID);
    float var  = sm[0].y * (1.0f/WID) - mean*mean;
    float rstd = rsqrtf(var + 1e-5f);

    float4 g4 = *(const float4*)(gg + tid*4);
    float4 b4 = *(const float4*)(bb + tid*4);
    float4 o;
    o.x = (tv.x - mean)*rstd*g4.x + b4.x;
    o.y = (tv.y - mean)*rstd*g4.y + b4.y;
    o.z = (tv.z - mean)*rstd*g4.z + b4.z;
    o.w = (tv.w - mean)*rstd*g4.w + b4.w;
    *(float4*)(out + row*WID + tid*4) = o;
    if (outr) {
        float* d = outr + row*WID + (size_t)(tid >> 1) * 8 + (tid & 1);
        d[0] = rtf(o.x); d[2] = rtf(o.y); d[4] = rtf(o.z); d[6] = rtf(o.w);
    }
}

// ---------------- masked max-pool: single pass, all 7 groups ----------------
// grid (4 col-blocks, 16 batch), 256 threads, 1 column per thread.
__global__ __launch_bounds__(256) void maxpool_fused(
    const float* __restrict__ hidden, const int* __restrict__ in_ids,
    const int* __restrict__ resp_ids, float* __restrict__ mp)
{
    const int b  = blockIdx.y;
    const int col = blockIdx.x * 256 + threadIdx.x;
    const int tid = threadIdx.x;
    __shared__ signed char grp[SEQ];

    for (int s = tid; s < SEQ; s += 256) {
        int p = -1;
        if (s < SIN) {
            int v = in_ids[b*SIN + s];
            if (v > 0) p = v - 1;            // positives pool into group v-1
        } else {
            if (resp_ids[b*SRES + (s - SIN + 1)] == 1) p = 6;
        }
        grp[s] = (signed char)p;
    }
    __syncthreads();

    float v0 = 0.f, v1 = 0.f, v2 = 0.f, v3 = 0.f, v4 = 0.f, v5 = 0.f, v6 = 0.f;
    const float* hp = hidden + (size_t)(b*SEQ) * WID + col;
    for (int s = 0; s < SEQ; s++) {
        int p = grp[s];
        if (p >= 0) {
            float h = hp[(size_t)s * WID];
            v0 = (p == 0) ? fmaxf(v0, h) : v0;
            v1 = (p == 1) ? fmaxf(v1, h) : v1;
            v2 = (p == 2) ? fmaxf(v2, h) : v2;
            v3 = (p == 3) ? fmaxf(v3, h) : v3;
            v4 = (p == 4) ? fmaxf(v4, h) : v4;
            v5 = (p == 5) ? fmaxf(v5, h) : v5;
            v6 = (p == 6) ? fmaxf(v6, h) : v6;
        }
    }
    mp[(size_t)(0*BATCH + b)*WID + col] = v0;
    mp[(size_t)(1*BATCH + b)*WID + col] = v1;
    mp[(size_t)(2*BATCH + b)*WID + col] = v2;
    mp[(size_t)(3*BATCH + b)*WID + col] = v3;
    mp[(size_t)(4*BATCH + b)*WID + col] = v4;
    mp[(size_t)(5*BATCH + b)*WID + col] = v5;
    mp[(size_t)(6*BATCH + b)*WID + col] = v6;
}

// ---------------- topic softmax + gather ----------------
__global__ __launch_bounds__(256) void topic_kernel(
    const float* __restrict__ mp, const float* __restrict__ tw,
    const float* __restrict__ tb, const float* __restrict__ table,
    float* __restrict__ ue)
{
    const int gb = blockIdx.x;
    const int tid = threadIdx.x;
    __shared__ float mpv[WID];
    __shared__ float probs[NTOP];
    __shared__ float logits[NTOP];

    *(float4*)&mpv[tid*4] = *(const float4*)(mp + (size_t)gb*WID + tid*4);
    __syncthreads();

    const int warp = tid >> 5, lane = tid & 31;
    for (int t = warp; t < NTOP; t += 8) {
        const float* wr = tw + (size_t)t * WID;
        float s = 0.0f;
        for (int w = lane; w < WID; w += 32) s = fmaf(mpv[w], wr[w], s);
        #pragma unroll
        for (int o = 16; o > 0; o >>= 1) s += __shfl_down_sync(0xffffffffu, s, o);
        if (lane == 0) logits[t] = s + tb[t];
    }
    __syncthreads();

    if (tid == 0) {
        float m = -1e30f;
        for (int t = 0; t < NTOP; t++) m = fmaxf(m, logits[t]);
        float sum = 0.0f;
        for (int t = 0; t < NTOP; t++) { float e = expf(logits[t] - m); probs[t] = e; sum += e; }
        float inv = 1.0f / sum;
        for (int t = 0; t < NTOP; t++) probs[t] *= inv;
    }
    __syncthreads();

    const int w = tid * 4;
    float4 a = make_float4(0.f, 0.f, 0.f, 0.f);
    for (int t = 0; t < NTOP; t++) {
        float p = probs[t];
        float4 tv = *(const float4*)(table + (size_t)t*WID + w);
        a.x = fmaf(p, tv.x, a.x); a.y = fmaf(p, tv.y, a.y);
        a.z = fmaf(p, tv.z, a.z); a.w = fmaf(p, tv.w, a.w);
    }
    *(float4*)(ue + (size_t)gb*WID + w) = a;
}

// ---------------- final output ----------------
__global__ __launch_bounds__(256) void out_kernel(
    const float* __restrict__ X, const int* __restrict__ in_ids,
    const int* __restrict__ resp_ids, const float* __restrict__ ue,
    float* __restrict__ out)
{
    const int bs = blockIdx.x;
    const int b = bs >> 9, s = bs & 511;
    int g = -1; float c = 0.0f;
    if (s < SIN) {
        int v = in_ids[b*SIN + s];
        if (v > 0)      { g = v - 1;   c = 1.0f; }
        else if (v < 0) { g = -v - 1;  c = 2.0f; }
    } else {
        int v = resp_ids[b*SRES + (s - SIN + 1)];
        if (v == 1)       { g = 6; c = 1.0f; }
        else if (v == -1) { g = 6; c = 2.0f; }
    }
    const int w = threadIdx.x * 4;
    float4 xv = *(const float4*)(X + (size_t)bs*WID + w);
    if (g >= 0) {
        float4 u = *(const float4*)(ue + (size_t)(g*BATCH + b)*WID + w);
        xv.x = fmaf(c, u.x, xv.x); xv.y = fmaf(c, u.y, xv.y);
        xv.z = fmaf(c, u.z, xv.z); xv.w = fmaf(c, u.w, xv.w);
    }
    *(float4*)(out + (size_t)bs*WID + w) = xv;
}

// ---------------- launch ----------------
extern "C" void kernel_launch(void* const* d_in, const int* in_sizes, int n_in,
                              void* d_out, int out_size)
{
    const float* X       = (const float*)d_in[0];
    const int*   in_ids  = (const int*)  d_in[1];
    const int*   resp_ids= (const int*)  d_in[2];
    const float* Wqkv    = (const float*)d_in[3];
    const float* bqkv    = (const float*)d_in[4];
    const float* Wo      = (const float*)d_in[5];
    const float* bo      = (const float*)d_in[6];
    const float* ln1g    = (const float*)d_in[7];
    const float* ln1b    = (const float*)d_in[8];
    const float* W1      = (const float*)d_in[9];
    const float* b1      = (const float*)d_in[10];
    const float* W2      = (const float*)d_in[11];
    const float* b2      = (const float*)d_in[12];
    const float* ln2g    = (const float*)d_in[13];
    const float* ln2b    = (const float*)d_in[14];
    const float* tw      = (const float*)d_in[15];
    const float* tb      = (const float*)d_in[16];
    const float* table   = (const float*)d_in[17];
    float* out = (float*)d_out;

    float *qkv, *ctx, *tmp, *y, *hid, *wr, *mp, *ue;
    cudaGetSymbolAddress((void**)&qkv, g_qkv);
    cudaGetSymbolAddress((void**)&ctx, g_ctx);
    cudaGetSymbolAddress((void**)&tmp, g_tmp);
    cudaGetSymbolAddress((void**)&y,   g_y);
    cudaGetSymbolAddress((void**)&hid, g_hid);
    cudaGetSymbolAddress((void**)&wr,  g_wr);
    cudaGetSymbolAddress((void**)&mp,  g_mp);
    cudaGetSymbolAddress((void**)&ue,  g_ue);

    float* wqkv_r = wr;                 // 3,145,728
    float* wo_r   = wr + 3145728;       // 1,048,576
    float* w1_r   = wr + 4194304;       // 4,194,304
    float* w2_r   = wr + 8388608;       // 4,194,304
    float* xr     = hid;                // rounded+permuted X (hid free until step 7)

    const int smem = NSTAGE * STAGE_F * 2 * sizeof(float);   // 98,304 B
    cudaFuncSetAttribute(mma_gemm, cudaFuncAttributeMaxDynamicSharedMemorySize, smem);

    // 0. round+permute X and all weights (counts in float8 units)
    round_perm_multi<<<8192, 256>>>(
        X,    xr,     (MROWS*WID)/8,
        Wqkv, wqkv_r, (3072*1024)/8,
        Wo,   wo_r,   (1024*1024)/8,
        W1,   w1_r,   (4096*1024)/8,
        W2,   w2_r,   (1024*4096)/8);

    // 1. QKV (round + permute output cols -> attention reads permuted d)
    mma_gemm<<<dim3(3072/BN, MROWS/BM), 128, smem>>>(xr, wqkv_r, bqkv, qkv, MROWS, 3072, 1024, 6);
    // 2. attention (ctx cols inherit permuted d-labels, rounded)
    attn_mma_kernel<<<dim3(SEQ/128, BATCH*HEADS), 256>>>(qkv, ctx);
    // 3. proj
    mma_gemm<<<dim3(WID/BN, MROWS/BM), 128, smem>>>(ctx, wo_r, bo, tmp, MROWS, WID, 1024, 0);
    // 4. y = LN(X + proj), plus rounded+permuted copy into ctx
    add_ln_kernel<<<MROWS, 256>>>(X, tmp, ln1g, ln1b, y, ctx);
    // 5. FF1 + GELU (round + permute -> FF2)
    mma_gemm<<<dim3(DFF/BN, MROWS/BM), 128, smem>>>(ctx, w1_r, b1, tmp, MROWS, DFF, 1024, 7);
    // 6. FF2
    mma_gemm<<<dim3(WID/BN, MROWS/BM), 128, smem>>>(tmp, w2_r, b2, ctx, MROWS, WID, 4096, 0);
    // 7. hidden = LN(y + FF2)
    add_ln_kernel<<<MROWS, 256>>>(y, ctx, ln2g, ln2b, hid, nullptr);
    // 8. masked max-pool: ONE pass over hidden for all 7 groups
    maxpool_fused<<<dim3(4, BATCH), 256>>>(hid, in_ids, resp_ids, mp);
    // 9-10. topic softmax/gather + final output
    topic_kernel<<<NGRP*BATCH, 256>>>(mp, tw, tb, table, ue);
    out_kernel<<<MROWS, 256>>>(X, in_ids, resp_ids, ue, out);
}